// round 7
// baseline (speedup 1.0000x reference)
#include <cuda_runtime.h>
#include <cuda_bf16.h>
#include <math.h>

// ---------------- problem constants ----------------
#define BB   2
#define SS   2048
#define HH   1024
#define NHH  16
#define HDD  64
#define LL   8
#define VV   32000
#define II   2730
#define IPAD 2752
#define MM   (BB*SS)

// ---------------- device scratch ----------------
__device__ float g_x [MM*HH];
__device__ float g_h [MM*HH];
__device__ float g_q [MM*HH];
__device__ float g_k [MM*HH];
__device__ float g_v [MM*HH];
__device__ float g_q2[MM*HH];
__device__ float g_k2[MM*HH];
__device__ float g_ao[MM*HH];
__device__ float g_g [MM*IPAD];
__device__ float g_u [MM*IPAD];

// ---------------- embedding gather ----------------
__global__ void embed_kernel(const int* __restrict__ ids,
                             const float* __restrict__ emb,
                             float* __restrict__ x)
{
    int idx = blockIdx.x * blockDim.x + threadIdx.x;
    if (idx >= MM*HH) return;
    int m = idx >> 10;
    int d = idx & 1023;
    x[idx] = emb[(size_t)ids[m] * HH + d];
}

// ---------------- layernorm ----------------
__global__ void ln_kernel(const float* __restrict__ x,
                          const float* __restrict__ w,
                          const float* __restrict__ b,
                          float* __restrict__ out)
{
    int row = blockIdx.x;
    const float* xr = x + (size_t)row * HH;
    float v[4], s = 0.f, sq = 0.f;
#pragma unroll
    for (int i = 0; i < 4; i++) {
        v[i] = xr[threadIdx.x + i*256];
        s  += v[i];
        sq += v[i]*v[i];
    }
    __shared__ float rs[8], rq[8];
    int lane = threadIdx.x & 31, wid = threadIdx.x >> 5;
#pragma unroll
    for (int off = 16; off > 0; off >>= 1) {
        s  += __shfl_xor_sync(0xffffffffu, s,  off);
        sq += __shfl_xor_sync(0xffffffffu, sq, off);
    }
    if (lane == 0) { rs[wid] = s; rq[wid] = sq; }
    __syncthreads();
    if (threadIdx.x == 0) {
        float ts = 0.f, tq = 0.f;
        for (int i = 0; i < 8; i++) { ts += rs[i]; tq += rq[i]; }
        rs[0] = ts; rq[0] = tq;
    }
    __syncthreads();
    float mu  = rs[0] * (1.f/HH);
    float var = rq[0] * (1.f/HH) - mu*mu;
    float inv = rsqrtf(var + 1e-5f);
    float* orow = out + (size_t)row * HH;
#pragma unroll
    for (int i = 0; i < 4; i++) {
        int d = threadIdx.x + i*256;
        orow[d] = (v[i] - mu) * inv * w[d] + b[d];
    }
}

// ---------------- RoPE v2: independent implementation, out-of-place ----------------
// Block = one token m (4096 blocks), 512 threads = head(16) x pair-index(32).
// invf = 10000^{-i/32} computed via expf(-i * ln(10000)/32).
__global__ __launch_bounds__(512)
void rope2_kernel(const float* __restrict__ qin, const float* __restrict__ kin,
                  float* __restrict__ qout, float* __restrict__ kout)
{
    const int m = blockIdx.x;          // token 0..MM-1
    const int t = threadIdx.x;         // 0..511
    const int head = t >> 5;           // 0..15
    const int i    = t & 31;           // pair index 0..31
    const int s    = m % SS;           // position within sequence

    const float LOG1E4_OVER_32 = 0.28782313662425f;  // ln(10000)/32
    float invf = expf(-(float)i * LOG1E4_OVER_32);
    float ang  = (float)s * invf;
    float c  = cosf(ang);
    float sn = sinf(ang);

    size_t base = (size_t)m * HH + head * HDD + i;
    float qa = qin[base], qb = qin[base + 32];
    qout[base]      = fmaf(qa, c, -qb * sn);
    qout[base + 32] = fmaf(qb, c,  qa * sn);
    float ka = kin[base], kb = kin[base + 32];
    kout[base]      = fmaf(ka, c, -kb * sn);
    kout[base + 32] = fmaf(kb, c,  ka * sn);
}

// ---------------- SiLU(gate) * up ----------------
__global__ void silu_kernel(float* __restrict__ g, const float* __restrict__ u)
{
    int c = blockIdx.x * blockDim.x + threadIdx.x;
    int m = blockIdx.y;
    if (c >= II) return;
    size_t a = (size_t)m * IPAD + c;
    float x = g[a];
    g[a] = x / (1.f + expf(-x)) * u[a];
}

// ---------------- fast SGEMM: C[M,N] = A[M,K] @ B (+C if ACC) ----------------
template<bool TB, bool ACC>
__global__ __launch_bounds__(256, 2)
void sgemm(const float* __restrict__ A, int lda,
           const float* __restrict__ B, int ldb,
           float* __restrict__ C, int ldc,
           int M, int N, int K)
{
    __shared__ __align__(16) float As[8][128];
    __shared__ __align__(16) float Bs[8][128];
    const int bm = blockIdx.y * 128, bn = blockIdx.x * 128;
    const int tid = threadIdx.x;
    const int tx = tid & 15, ty = tid >> 4;

    float acc[8][8];
#pragma unroll
    for (int i = 0; i < 8; i++)
#pragma unroll
        for (int j = 0; j < 8; j++) acc[i][j] = 0.f;

    const int arow = tid >> 1, ak = (tid & 1) * 4;

    for (int k0 = 0; k0 < K; k0 += 8) {
#pragma unroll
        for (int i = 0; i < 4; i++) {
            int kk = k0 + ak + i;
            int mr = bm + arow;
            As[ak+i][arow] = (kk < K && mr < M) ? A[(size_t)mr*lda + kk] : 0.f;
        }
        if (TB) {
            int nr = tid >> 1, bk = (tid & 1) * 4;
#pragma unroll
            for (int i = 0; i < 4; i++) {
                int kk = k0 + bk + i, nn = bn + nr;
                Bs[bk+i][nr] = (kk < K && nn < N) ? B[(size_t)nn*ldb + kk] : 0.f;
            }
        } else {
            int bk = tid >> 5, nc = (tid & 31) * 4;
#pragma unroll
            for (int i = 0; i < 4; i++) {
                int kk = k0 + bk, nn = bn + nc + i;
                Bs[bk][nc+i] = (kk < K && nn < N) ? B[(size_t)kk*ldb + nn] : 0.f;
            }
        }
        __syncthreads();
#pragma unroll
        for (int kk = 0; kk < 8; kk++) {
            float4 a0 = *(const float4*)&As[kk][ty*8];
            float4 a1 = *(const float4*)&As[kk][ty*8+4];
            float4 b0 = *(const float4*)&Bs[kk][tx*8];
            float4 b1 = *(const float4*)&Bs[kk][tx*8+4];
            float av[8] = {a0.x,a0.y,a0.z,a0.w,a1.x,a1.y,a1.z,a1.w};
            float bv[8] = {b0.x,b0.y,b0.z,b0.w,b1.x,b1.y,b1.z,b1.w};
#pragma unroll
            for (int i = 0; i < 8; i++)
#pragma unroll
                for (int j = 0; j < 8; j++)
                    acc[i][j] += av[i]*bv[j];
        }
        __syncthreads();
    }

#pragma unroll
    for (int i = 0; i < 8; i++) {
        int row = bm + ty*8 + i;
        if (row >= M) continue;
#pragma unroll
        for (int jj = 0; jj < 8; jj += 4) {
            int col = bn + tx*8 + jj;
            if (col + 3 < N) {
                float4* p = (float4*)&C[(size_t)row*ldc + col];
                float4 vv;
                vv.x = acc[i][jj];   vv.y = acc[i][jj+1];
                vv.z = acc[i][jj+2]; vv.w = acc[i][jj+3];
                if (ACC) { float4 o = *p; vv.x+=o.x; vv.y+=o.y; vv.z+=o.z; vv.w+=o.w; }
                *p = vv;
            } else {
                for (int j = jj; j < jj+4; j++) {
                    int c2 = bn + tx*8 + j;
                    if (c2 < N) {
                        float t = acc[i][j];
                        if (ACC) t += C[(size_t)row*ldc + c2];
                        C[(size_t)row*ldc + c2] = t;
                    }
                }
            }
        }
    }
}

// ---------------- flash attention ----------------
__global__ __launch_bounds__(256)
void attn_kernel(const float* __restrict__ q, const float* __restrict__ k,
                 const float* __restrict__ v, const int* __restrict__ ids,
                 float* __restrict__ out)
{
    __shared__ __align__(16) float QT[64][65];
    __shared__ __align__(16) float KT[64][33];
    __shared__ __align__(16) float Ps[32][65];
    __shared__ __align__(16) float Vs[32][64];
    __shared__ float pads[32];

    const int b  = blockIdx.z, h = blockIdx.y, q0 = blockIdx.x * 64;
    const int tid = threadIdx.x;
    const int sx = tid & 15, sy = tid >> 4;
    const size_t hoff = (size_t)h * HDD;

    for (int i2 = tid; i2 < 64*64; i2 += 256) {
        int r = i2 >> 6, d = i2 & 63;
        QT[d][r] = q[((size_t)(b*SS + q0 + r))*HH + hoff + d];
    }
    float m[4], l[4], o[4][4];
#pragma unroll
    for (int i = 0; i < 4; i++) {
        m[i] = -3e38f; l[i] = 0.f;
#pragma unroll
        for (int j = 0; j < 4; j++) o[i][j] = 0.f;
    }
    __syncthreads();

    const int nk = q0 + 64;
    for (int c0 = 0; c0 < nk; c0 += 32) {
        for (int i2 = tid; i2 < 32*64; i2 += 256) {
            int c = i2 >> 6, d = i2 & 63;
            KT[d][c] = k[((size_t)(b*SS + c0 + c))*HH + hoff + d];
        }
        if (tid < 32)
            pads[tid] = (ids[b*SS + c0 + tid] != 0) ? 0.f : -10000.f;
        __syncthreads();

        float sv[4][2];
#pragma unroll
        for (int i = 0; i < 4; i++) { sv[i][0] = 0.f; sv[i][1] = 0.f; }
#pragma unroll 4
        for (int d = 0; d < 64; d++) {
            float a0 = QT[d][sy*4+0], a1 = QT[d][sy*4+1];
            float a2 = QT[d][sy*4+2], a3 = QT[d][sy*4+3];
            float b0 = KT[d][sx*2+0], b1 = KT[d][sx*2+1];
            sv[0][0] += a0*b0; sv[0][1] += a0*b1;
            sv[1][0] += a1*b0; sv[1][1] += a1*b1;
            sv[2][0] += a2*b0; sv[2][1] += a2*b1;
            sv[3][0] += a3*b0; sv[3][1] += a3*b1;
        }

        float corr[4];
#pragma unroll
        for (int i = 0; i < 4; i++) {
            int qrow = q0 + sy*4 + i;
#pragma unroll
            for (int j = 0; j < 2; j++) {
                int cc = c0 + sx*2 + j;
                float s_ = sv[i][j]*0.125f + pads[sx*2+j];
                if (cc > qrow) s_ = -3e38f;
                sv[i][j] = s_;
            }
            float tmax = fmaxf(sv[i][0], sv[i][1]);
#pragma unroll
            for (int off = 8; off > 0; off >>= 1)
                tmax = fmaxf(tmax, __shfl_xor_sync(0xffffffffu, tmax, off));
            float mn = fmaxf(m[i], tmax);
            corr[i] = expf(m[i] - mn);
            m[i] = mn;
            float p0 = expf(sv[i][0] - mn);
            float p1 = expf(sv[i][1] - mn);
            float rs = p0 + p1;
#pragma unroll
            for (int off = 8; off > 0; off >>= 1)
                rs += __shfl_xor_sync(0xffffffffu, rs, off);
            l[i] = l[i]*corr[i] + rs;
            Ps[sx*2+0][sy*4+i] = p0;
            Ps[sx*2+1][sy*4+i] = p1;
#pragma unroll
            for (int j = 0; j < 4; j++) o[i][j] *= corr[i];
        }
        __syncthreads();

        for (int i2 = tid; i2 < 32*64; i2 += 256) {
            int c = i2 >> 6, d = i2 & 63;
            Vs[c][d] = v[((size_t)(b*SS + c0 + c))*HH + hoff + d];
        }
        __syncthreads();

#pragma unroll 4
        for (int c = 0; c < 32; c++) {
            float p0 = Ps[c][sy*4+0], p1 = Ps[c][sy*4+1];
            float p2 = Ps[c][sy*4+2], p3 = Ps[c][sy*4+3];
            float4 vv = *(const float4*)&Vs[c][sx*4];
            o[0][0] += p0*vv.x; o[0][1] += p0*vv.y; o[0][2] += p0*vv.z; o[0][3] += p0*vv.w;
            o[1][0] += p1*vv.x; o[1][1] += p1*vv.y; o[1][2] += p1*vv.z; o[1][3] += p1*vv.w;
            o[2][0] += p2*vv.x; o[2][1] += p2*vv.y; o[2][2] += p2*vv.z; o[2][3] += p2*vv.w;
            o[3][0] += p3*vv.x; o[3][1] += p3*vv.y; o[3][2] += p3*vv.z; o[3][3] += p3*vv.w;
        }
        __syncthreads();
    }

#pragma unroll
    for (int i = 0; i < 4; i++) {
        float inv = 1.f / l[i];
        float4 res;
        res.x = o[i][0]*inv; res.y = o[i][1]*inv;
        res.z = o[i][2]*inv; res.w = o[i][3]*inv;
        *(float4*)&out[((size_t)(b*SS + q0 + sy*4 + i))*HH + hoff + sx*4] = res;
    }
}

// ---------------- launch ----------------
extern "C" void kernel_launch(void* const* d_in, const int* in_sizes, int n_in,
                              void* d_out, int out_size)
{
    if (n_in != 15) return;
    const int expect[15] = {
        MM, VV*HH,
        LL*HH*HH, LL*HH*HH, LL*HH*HH, LL*HH*HH,
        LL*HH*II, LL*HH*II, LL*II*HH,
        LL*HH, LL*HH, LL*HH, LL*HH,
        HH, HH
    };
    for (int i = 0; i < 15; i++)
        if (in_sizes[i] != expect[i]) return;

    const int*   ids    = (const int*)  d_in[0];
    const float* emb    = (const float*)d_in[1];
    const float* q_w    = (const float*)d_in[2];
    const float* k_w    = (const float*)d_in[3];
    const float* v_w    = (const float*)d_in[4];
    const float* o_w    = (const float*)d_in[5];
    const float* gate_w = (const float*)d_in[6];
    const float* up_w   = (const float*)d_in[7];
    const float* down_w = (const float*)d_in[8];
    const float* ln1_w  = (const float*)d_in[9];
    const float* ln1_b  = (const float*)d_in[10];
    const float* ln2_w  = (const float*)d_in[11];
    const float* ln2_b  = (const float*)d_in[12];
    const float* lnf_w  = (const float*)d_in[13];
    const float* lnf_b  = (const float*)d_in[14];
    float* out = (float*)d_out;

    float *px, *ph, *pq, *pk, *pv, *pq2, *pk2, *pao, *pg, *pu;
    cudaGetSymbolAddress((void**)&px,  g_x);
    cudaGetSymbolAddress((void**)&ph,  g_h);
    cudaGetSymbolAddress((void**)&pq,  g_q);
    cudaGetSymbolAddress((void**)&pk,  g_k);
    cudaGetSymbolAddress((void**)&pv,  g_v);
    cudaGetSymbolAddress((void**)&pq2, g_q2);
    cudaGetSymbolAddress((void**)&pk2, g_k2);
    cudaGetSymbolAddress((void**)&pao, g_ao);
    cudaGetSymbolAddress((void**)&pg,  g_g);
    cudaGetSymbolAddress((void**)&pu,  g_u);

    embed_kernel<<<(MM*HH + 255)/256, 256>>>(ids, emb, px);

    dim3 gqkv(HH/128, MM/128);
    dim3 gffn((II + 127)/128, MM/128);
    dim3 gattn(SS/64, NHH, BB);
    dim3 gsilu((II + 255)/256, MM);

    for (int l = 0; l < LL; l++) {
        const float* qw = q_w    + (size_t)l*HH*HH;
        const float* kw = k_w    + (size_t)l*HH*HH;
        const float* vw = v_w    + (size_t)l*HH*HH;
        const float* ow = o_w    + (size_t)l*HH*HH;
        const float* gw = gate_w + (size_t)l*HH*II;
        const float* uw = up_w   + (size_t)l*HH*II;
        const float* dw = down_w + (size_t)l*II*HH;

        ln_kernel<<<MM, 256>>>(px, ln1_w + l*HH, ln1_b + l*HH, ph);

        sgemm<false,false><<<gqkv, 256>>>(ph, HH, qw, HH, pq, HH, MM, HH, HH);
        sgemm<false,false><<<gqkv, 256>>>(ph, HH, kw, HH, pk, HH, MM, HH, HH);
        sgemm<false,false><<<gqkv, 256>>>(ph, HH, vw, HH, pv, HH, MM, HH, HH);

        // RoPE v2: independent implementation, out-of-place
        rope2_kernel<<<MM, 512>>>(pq, pk, pq2, pk2);

        attn_kernel<<<gattn, 256>>>(pq2, pk2, pv, ids, pao);

        sgemm<false,true><<<gqkv, 256>>>(pao, HH, ow, HH, px, HH, MM, HH, HH);

        ln_kernel<<<MM, 256>>>(px, ln2_w + l*HH, ln2_b + l*HH, ph);

        sgemm<false,false><<<gffn, 256>>>(ph, HH, gw, II, pg, IPAD, MM, II, HH);
        sgemm<false,false><<<gffn, 256>>>(ph, HH, uw, II, pu, IPAD, MM, II, HH);

        silu_kernel<<<gsilu, 256>>>(pg, pu);

        sgemm<false,true><<<gqkv, 256>>>(pg, IPAD, dw, HH, px, HH, MM, HH, II);
    }

    ln_kernel<<<MM, 256>>>(px, lnf_w, lnf_b, ph);

    dim3 glog(VV/128, MM/128);
    sgemm<true,false><<<glog, 256>>>(ph, HH, emb, HH, out, VV, MM, VV, HH);
}

// round 8
// speedup vs baseline: 2.3972x; 2.3972x over previous
#include <cuda_runtime.h>
#include <cuda_bf16.h>
#include <math.h>

// ---------------- problem constants ----------------
#define BB   2
#define SS   2048
#define HH   1024
#define NHH  16
#define HDD  64
#define LL   8
#define VV   32000
#define II   2730
#define IPAD 2752
#define MM   (BB*SS)

// ---------------- device scratch ----------------
__device__ float g_x [MM*HH];
__device__ float g_h [MM*HH];
__device__ float g_q [MM*HH];
__device__ float g_k [MM*HH];
__device__ float g_v [MM*HH];
__device__ float g_q2[MM*HH];
__device__ float g_k2[MM*HH];
__device__ float g_ao[MM*HH];
__device__ float g_g [MM*IPAD];
__device__ float g_u [MM*IPAD];

// bf16 split buffers (A3 = [hi|lo|hi], B3 = [hi|hi|lo] along K)
__device__ __nv_bfloat16 g_a3[(size_t)MM*3072];     // acts with K=1024
__device__ __nv_bfloat16 g_g3[(size_t)MM*8192];     // FFN act (K=2730 -> K3pad 8192)
__device__ __nv_bfloat16 g_b3[(size_t)2816*3072];   // per-GEMM weight scratch
__device__ __nv_bfloat16 g_e3[(size_t)VV*3072];     // emb for logits

// ---------------- embedding gather ----------------
__global__ void embed_kernel(const int* __restrict__ ids,
                             const float* __restrict__ emb,
                             float* __restrict__ x)
{
    int idx = blockIdx.x * blockDim.x + threadIdx.x;
    if (idx >= MM*HH) return;
    int m = idx >> 10;
    int d = idx & 1023;
    x[idx] = emb[(size_t)ids[m] * HH + d];
}

// ---------------- layernorm ----------------
__global__ void ln_kernel(const float* __restrict__ x,
                          const float* __restrict__ w,
                          const float* __restrict__ b,
                          float* __restrict__ out)
{
    int row = blockIdx.x;
    const float* xr = x + (size_t)row * HH;
    float v[4], s = 0.f, sq = 0.f;
#pragma unroll
    for (int i = 0; i < 4; i++) {
        v[i] = xr[threadIdx.x + i*256];
        s  += v[i];
        sq += v[i]*v[i];
    }
    __shared__ float rs[8], rq[8];
    int lane = threadIdx.x & 31, wid = threadIdx.x >> 5;
#pragma unroll
    for (int off = 16; off > 0; off >>= 1) {
        s  += __shfl_xor_sync(0xffffffffu, s,  off);
        sq += __shfl_xor_sync(0xffffffffu, sq, off);
    }
    if (lane == 0) { rs[wid] = s; rq[wid] = sq; }
    __syncthreads();
    if (threadIdx.x == 0) {
        float ts = 0.f, tq = 0.f;
        for (int i = 0; i < 8; i++) { ts += rs[i]; tq += rq[i]; }
        rs[0] = ts; rq[0] = tq;
    }
    __syncthreads();
    float mu  = rs[0] * (1.f/HH);
    float var = rq[0] * (1.f/HH) - mu*mu;
    float inv = rsqrtf(var + 1e-5f);
    float* orow = out + (size_t)row * HH;
#pragma unroll
    for (int i = 0; i < 4; i++) {
        int d = threadIdx.x + i*256;
        orow[d] = (v[i] - mu) * inv * w[d] + b[d];
    }
}

// ---------------- RoPE v2 (the proven-correct one) ----------------
__global__ __launch_bounds__(512)
void rope2_kernel(const float* __restrict__ qin, const float* __restrict__ kin,
                  float* __restrict__ qout, float* __restrict__ kout)
{
    const int m = blockIdx.x;
    const int t = threadIdx.x;
    const int head = t >> 5;
    const int i    = t & 31;
    const int s    = m % SS;

    const float LOG1E4_OVER_32 = 0.28782313662425f;
    float invf = expf(-(float)i * LOG1E4_OVER_32);
    float ang  = (float)s * invf;
    float c  = cosf(ang);
    float sn = sinf(ang);

    size_t base = (size_t)m * HH + head * HDD + i;
    float qa = qin[base], qb = qin[base + 32];
    qout[base]      = fmaf(qa, c, -qb * sn);
    qout[base + 32] = fmaf(qb, c,  qa * sn);
    float ka = kin[base], kb = kin[base + 32];
    kout[base]      = fmaf(ka, c, -kb * sn);
    kout[base + 32] = fmaf(kb, c,  ka * sn);
}

// ---------------- SiLU(gate) * up ----------------
__global__ void silu_kernel(float* __restrict__ g, const float* __restrict__ u)
{
    int c = blockIdx.x * blockDim.x + threadIdx.x;
    int m = blockIdx.y;
    if (c >= II) return;
    size_t a = (size_t)m * IPAD + c;
    float x = g[a];
    g[a] = x / (1.f + expf(-x)) * u[a];
}

// ---------------- bf16 split conversions ----------------
// activation: A[M][ld] fp32 -> A3[M][ld3] bf16 segments [hi | lo | hi], pad zeros
__global__ void split_act(const float* __restrict__ A, int ld, int K,
                          __nv_bfloat16* __restrict__ A3, int ld3, int total)
{
    int idx = blockIdx.x*256 + threadIdx.x;
    if (idx >= total) return;
    int m = idx / K, k = idx - m*K;
    float x = A[(size_t)m*ld + k];
    __nv_bfloat16 h = __float2bfloat16(x);
    __nv_bfloat16 l = __float2bfloat16(x - __bfloat162float(h));
    size_t base = (size_t)m*ld3;
    A3[base + k]       = h;
    A3[base + K + k]   = l;
    A3[base + 2*K + k] = h;
    int pad = ld3 - 3*K;
    if (k < pad) A3[base + 3*K + k] = __float2bfloat16(0.f);
}

// weight: W[K][N] fp32 (row stride N) -> B3[Npad][ld3] bf16 [hi | hi | lo], transposed
__global__ void split_w(const float* __restrict__ W, int K, int N, int Npad,
                        __nv_bfloat16* __restrict__ B3, int ld3, int total)
{
    int idx = blockIdx.x*256 + threadIdx.x;
    if (idx >= total) return;                 // total = Npad*K
    int n = idx / K, k = idx - n*K;
    float x = (n < N) ? W[(size_t)k*N + n] : 0.f;
    __nv_bfloat16 h = __float2bfloat16(x);
    __nv_bfloat16 l = __float2bfloat16(x - __bfloat162float(h));
    size_t base = (size_t)n*ld3;
    B3[base + k]       = h;
    B3[base + K + k]   = h;
    B3[base + 2*K + k] = l;
    int pad = ld3 - 3*K;
    if (k < pad) B3[base + 3*K + k] = __float2bfloat16(0.f);
}

// emb: [V][H] fp32 -> g_e3[V][3072] (no transpose; emb already [n][k])
__global__ void split_emb(const float* __restrict__ E, __nv_bfloat16* __restrict__ E3)
{
    int idx = blockIdx.x*256 + threadIdx.x;
    if (idx >= VV*HH) return;
    int n = idx >> 10, k = idx & 1023;
    float x = E[idx];
    __nv_bfloat16 h = __float2bfloat16(x);
    __nv_bfloat16 l = __float2bfloat16(x - __bfloat162float(h));
    size_t base = (size_t)n*3072;
    E3[base + k]        = h;
    E3[base + 1024 + k] = h;
    E3[base + 2048 + k] = l;
}

// ---------------- tensor-core GEMM: C[M,N] (+)= A3[M,K3] @ B3[N,K3]^T ----------------
// A3 row-major bf16, B3 row-major bf16 (i.e. B transposed), fp32 accum.
// 128x128x32 tiles, 8 warps (2x4), warp tile 64x32, mma.m16n8k16, 3-stage cp.async.
__device__ __forceinline__ unsigned swzoff(int row, int ch)  // byte offset in a 128x32 bf16 tile
{
    return (unsigned)(row*64 + ((ch ^ ((row>>1)&3)) << 4));
}

__global__ __launch_bounds__(256)
void bgemm(const __nv_bfloat16* __restrict__ A3, int lda,
           const __nv_bfloat16* __restrict__ B3, int ldb,
           float* __restrict__ C, int ldc,
           int N, int K3, int ACC)
{
    __shared__ __align__(16) __nv_bfloat16 smA[3][128*32];
    __shared__ __align__(16) __nv_bfloat16 smB[3][128*32];

    const int tid  = threadIdx.x;
    const int lane = tid & 31, warp = tid >> 5;
    const int wm = warp >> 2, wn = warp & 3;
    const int bm = blockIdx.y * 128, bn = blockIdx.x * 128;

    const unsigned sA0 = (unsigned)__cvta_generic_to_shared(&smA[0][0]);
    const unsigned sB0 = (unsigned)__cvta_generic_to_shared(&smB[0][0]);

    float acc[4][4][4];
#pragma unroll
    for (int i = 0; i < 4; i++)
#pragma unroll
        for (int j = 0; j < 4; j++)
#pragma unroll
            for (int r = 0; r < 4; r++) acc[i][j][r] = 0.f;

    const int S = K3 >> 5;

    auto issue = [&](int s) {
        const int buf = s % 3;
        const int k0  = s << 5;
#pragma unroll
        for (int i = 0; i < 2; i++) {
            int idx = i*256 + tid;               // 0..511
            int row = idx >> 2, ch = idx & 3;
            unsigned so = (unsigned)(buf*8192) + swzoff(row, ch);
            const __nv_bfloat16* ga = A3 + (size_t)(bm+row)*lda + k0 + ch*8;
            asm volatile("cp.async.cg.shared.global [%0], [%1], 16;\n" :: "r"(sA0+so), "l"(ga));
            const __nv_bfloat16* gb = B3 + (size_t)(bn+row)*ldb + k0 + ch*8;
            asm volatile("cp.async.cg.shared.global [%0], [%1], 16;\n" :: "r"(sB0+so), "l"(gb));
        }
        asm volatile("cp.async.commit_group;\n" ::);
    };

    issue(0); issue(1);

    for (int s = 0; s < S; s++) {
        if (s + 1 < S) asm volatile("cp.async.wait_group 1;\n" ::);
        else           asm volatile("cp.async.wait_group 0;\n" ::);
        __syncthreads();
        if (s + 2 < S) issue(s + 2);

        const int buf = s % 3;
        const unsigned baseA = sA0 + (unsigned)(buf*8192);
        const unsigned baseB = sB0 + (unsigned)(buf*8192);
#pragma unroll
        for (int ks = 0; ks < 2; ks++) {
            const int c0 = ks*2;
            unsigned a[4][4], b[4][2];
#pragma unroll
            for (int mt = 0; mt < 4; mt++) {
                int row = wm*64 + mt*16 + (lane & 7) + ((lane >> 3) & 1)*8;
                int ch  = c0 + (lane >> 4);
                unsigned ad = baseA + swzoff(row, ch);
                asm volatile("ldmatrix.sync.aligned.m8n8.x4.shared.b16 {%0,%1,%2,%3}, [%4];"
                    : "=r"(a[mt][0]), "=r"(a[mt][1]), "=r"(a[mt][2]), "=r"(a[mt][3]) : "r"(ad));
            }
#pragma unroll
            for (int p = 0; p < 2; p++) {
                int row = wn*32 + p*16 + (lane & 7) + ((lane >> 4) & 1)*8;
                int ch  = c0 + ((lane >> 3) & 1);
                unsigned ad = baseB + swzoff(row, ch);
                unsigned r0, r1, r2, r3;
                asm volatile("ldmatrix.sync.aligned.m8n8.x4.shared.b16 {%0,%1,%2,%3}, [%4];"
                    : "=r"(r0), "=r"(r1), "=r"(r2), "=r"(r3) : "r"(ad));
                b[2*p][0] = r0; b[2*p][1] = r1; b[2*p+1][0] = r2; b[2*p+1][1] = r3;
            }
#pragma unroll
            for (int mt = 0; mt < 4; mt++)
#pragma unroll
                for (int nt = 0; nt < 4; nt++)
                    asm volatile("mma.sync.aligned.m16n8k16.row.col.f32.bf16.bf16.f32 "
                        "{%0,%1,%2,%3}, {%4,%5,%6,%7}, {%8,%9}, {%0,%1,%2,%3};"
                        : "+f"(acc[mt][nt][0]), "+f"(acc[mt][nt][1]),
                          "+f"(acc[mt][nt][2]), "+f"(acc[mt][nt][3])
                        : "r"(a[mt][0]), "r"(a[mt][1]), "r"(a[mt][2]), "r"(a[mt][3]),
                          "r"(b[nt][0]), "r"(b[nt][1]));
        }
    }

    // epilogue
#pragma unroll
    for (int mt = 0; mt < 4; mt++) {
        int grow = bm + wm*64 + mt*16 + (lane >> 2);
#pragma unroll
        for (int nt = 0; nt < 4; nt++) {
            int gcol = bn + wn*32 + nt*8 + 2*(lane & 3);
            if (gcol < N) {
                float2* p0 = (float2*)&C[(size_t)grow*ldc + gcol];
                float2* p1 = (float2*)&C[(size_t)(grow+8)*ldc + gcol];
                float2 v0 = make_float2(acc[mt][nt][0], acc[mt][nt][1]);
                float2 v1 = make_float2(acc[mt][nt][2], acc[mt][nt][3]);
                if (ACC) {
                    float2 o0 = *p0, o1 = *p1;
                    v0.x += o0.x; v0.y += o0.y; v1.x += o1.x; v1.y += o1.y;
                }
                *p0 = v0; *p1 = v1;
            }
        }
    }
}

// ---------------- flash attention (unchanged, proven) ----------------
__global__ __launch_bounds__(256)
void attn_kernel(const float* __restrict__ q, const float* __restrict__ k,
                 const float* __restrict__ v, const int* __restrict__ ids,
                 float* __restrict__ out)
{
    __shared__ __align__(16) float QT[64][65];
    __shared__ __align__(16) float KT[64][33];
    __shared__ __align__(16) float Ps[32][65];
    __shared__ __align__(16) float Vs[32][64];
    __shared__ float pads[32];

    const int b  = blockIdx.z, h = blockIdx.y, q0 = blockIdx.x * 64;
    const int tid = threadIdx.x;
    const int sx = tid & 15, sy = tid >> 4;
    const size_t hoff = (size_t)h * HDD;

    for (int i2 = tid; i2 < 64*64; i2 += 256) {
        int r = i2 >> 6, d = i2 & 63;
        QT[d][r] = q[((size_t)(b*SS + q0 + r))*HH + hoff + d];
    }
    float m[4], l[4], o[4][4];
#pragma unroll
    for (int i = 0; i < 4; i++) {
        m[i] = -3e38f; l[i] = 0.f;
#pragma unroll
        for (int j = 0; j < 4; j++) o[i][j] = 0.f;
    }
    __syncthreads();

    const int nk = q0 + 64;
    for (int c0 = 0; c0 < nk; c0 += 32) {
        for (int i2 = tid; i2 < 32*64; i2 += 256) {
            int c = i2 >> 6, d = i2 & 63;
            KT[d][c] = k[((size_t)(b*SS + c0 + c))*HH + hoff + d];
        }
        if (tid < 32)
            pads[tid] = (ids[b*SS + c0 + tid] != 0) ? 0.f : -10000.f;
        __syncthreads();

        float sv[4][2];
#pragma unroll
        for (int i = 0; i < 4; i++) { sv[i][0] = 0.f; sv[i][1] = 0.f; }
#pragma unroll 4
        for (int d = 0; d < 64; d++) {
            float a0 = QT[d][sy*4+0], a1 = QT[d][sy*4+1];
            float a2 = QT[d][sy*4+2], a3 = QT[d][sy*4+3];
            float b0 = KT[d][sx*2+0], b1 = KT[d][sx*2+1];
            sv[0][0] += a0*b0; sv[0][1] += a0*b1;
            sv[1][0] += a1*b0; sv[1][1] += a1*b1;
            sv[2][0] += a2*b0; sv[2][1] += a2*b1;
            sv[3][0] += a3*b0; sv[3][1] += a3*b1;
        }

        float corr[4];
#pragma unroll
        for (int i = 0; i < 4; i++) {
            int qrow = q0 + sy*4 + i;
#pragma unroll
            for (int j = 0; j < 2; j++) {
                int cc = c0 + sx*2 + j;
                float s_ = sv[i][j]*0.125f + pads[sx*2+j];
                if (cc > qrow) s_ = -3e38f;
                sv[i][j] = s_;
            }
            float tmax = fmaxf(sv[i][0], sv[i][1]);
#pragma unroll
            for (int off = 8; off > 0; off >>= 1)
                tmax = fmaxf(tmax, __shfl_xor_sync(0xffffffffu, tmax, off));
            float mn = fmaxf(m[i], tmax);
            corr[i] = expf(m[i] - mn);
            m[i] = mn;
            float p0 = expf(sv[i][0] - mn);
            float p1 = expf(sv[i][1] - mn);
            float rs = p0 + p1;
#pragma unroll
            for (int off = 8; off > 0; off >>= 1)
                rs += __shfl_xor_sync(0xffffffffu, rs, off);
            l[i] = l[i]*corr[i] + rs;
            Ps[sx*2+0][sy*4+i] = p0;
            Ps[sx*2+1][sy*4+i] = p1;
#pragma unroll
            for (int j = 0; j < 4; j++) o[i][j] *= corr[i];
        }
        __syncthreads();

        for (int i2 = tid; i2 < 32*64; i2 += 256) {
            int c = i2 >> 6, d = i2 & 63;
            Vs[c][d] = v[((size_t)(b*SS + c0 + c))*HH + hoff + d];
        }
        __syncthreads();

#pragma unroll 4
        for (int c = 0; c < 32; c++) {
            float p0 = Ps[c][sy*4+0], p1 = Ps[c][sy*4+1];
            float p2 = Ps[c][sy*4+2], p3 = Ps[c][sy*4+3];
            float4 vv = *(const float4*)&Vs[c][sx*4];
            o[0][0] += p0*vv.x; o[0][1] += p0*vv.y; o[0][2] += p0*vv.z; o[0][3] += p0*vv.w;
            o[1][0] += p1*vv.x; o[1][1] += p1*vv.y; o[1][2] += p1*vv.z; o[1][3] += p1*vv.w;
            o[2][0] += p2*vv.x; o[2][1] += p2*vv.y; o[2][2] += p2*vv.z; o[2][3] += p2*vv.w;
            o[3][0] += p3*vv.x; o[3][1] += p3*vv.y; o[3][2] += p3*vv.z; o[3][3] += p3*vv.w;
        }
        __syncthreads();
    }

#pragma unroll
    for (int i = 0; i < 4; i++) {
        float inv = 1.f / l[i];
        float4 res;
        res.x = o[i][0]*inv; res.y = o[i][1]*inv;
        res.z = o[i][2]*inv; res.w = o[i][3]*inv;
        *(float4*)&out[((size_t)(b*SS + q0 + sy*4 + i))*HH + hoff + sx*4] = res;
    }
}

// ---------------- launch ----------------
extern "C" void kernel_launch(void* const* d_in, const int* in_sizes, int n_in,
                              void* d_out, int out_size)
{
    if (n_in != 15) return;
    const int expect[15] = {
        MM, VV*HH,
        LL*HH*HH, LL*HH*HH, LL*HH*HH, LL*HH*HH,
        LL*HH*II, LL*HH*II, LL*II*HH,
        LL*HH, LL*HH, LL*HH, LL*HH,
        HH, HH
    };
    for (int i = 0; i < 15; i++)
        if (in_sizes[i] != expect[i]) return;

    const int*   ids    = (const int*)  d_in[0];
    const float* emb    = (const float*)d_in[1];
    const float* q_w    = (const float*)d_in[2];
    const float* k_w    = (const float*)d_in[3];
    const float* v_w    = (const float*)d_in[4];
    const float* o_w    = (const float*)d_in[5];
    const float* gate_w = (const float*)d_in[6];
    const float* up_w   = (const float*)d_in[7];
    const float* down_w = (const float*)d_in[8];
    const float* ln1_w  = (const float*)d_in[9];
    const float* ln1_b  = (const float*)d_in[10];
    const float* ln2_w  = (const float*)d_in[11];
    const float* ln2_b  = (const float*)d_in[12];
    const float* lnf_w  = (const float*)d_in[13];
    const float* lnf_b  = (const float*)d_in[14];
    float* out = (float*)d_out;

    float *px, *ph, *pq, *pk, *pv, *pq2, *pk2, *pao, *pg, *pu;
    __nv_bfloat16 *pa3, *pg3, *pb3, *pe3;
    cudaGetSymbolAddress((void**)&px,  g_x);
    cudaGetSymbolAddress((void**)&ph,  g_h);
    cudaGetSymbolAddress((void**)&pq,  g_q);
    cudaGetSymbolAddress((void**)&pk,  g_k);
    cudaGetSymbolAddress((void**)&pv,  g_v);
    cudaGetSymbolAddress((void**)&pq2, g_q2);
    cudaGetSymbolAddress((void**)&pk2, g_k2);
    cudaGetSymbolAddress((void**)&pao, g_ao);
    cudaGetSymbolAddress((void**)&pg,  g_g);
    cudaGetSymbolAddress((void**)&pu,  g_u);
    cudaGetSymbolAddress((void**)&pa3, g_a3);
    cudaGetSymbolAddress((void**)&pg3, g_g3);
    cudaGetSymbolAddress((void**)&pb3, g_b3);
    cudaGetSymbolAddress((void**)&pe3, g_e3);

    embed_kernel<<<(MM*HH + 255)/256, 256>>>(ids, emb, px);
    split_emb<<<(VV*HH + 255)/256, 256>>>(emb, pe3);

    const int TACT  = MM*HH;        // 4096*1024
    const int TACTG = MM*II;        // 4096*2730
    const int TWQ   = HH*HH;        // 1024*1024 (Npad*K for qkv/o)
    const int TWGU  = 2816*HH;      // gate/up Npad*K
    const int TWD   = HH*II;        // down Npad*K = 1024*2730

    dim3 gqkv(8, 32);               // N=1024
    dim3 ggu(22, 32);               // Npad=2816
    dim3 glog(250, 32);             // N=32000
    dim3 gattn(SS/64, NHH, BB);
    dim3 gsilu((II + 255)/256, MM);

    for (int l = 0; l < LL; l++) {
        const float* qw = q_w    + (size_t)l*HH*HH;
        const float* kw = k_w    + (size_t)l*HH*HH;
        const float* vw = v_w    + (size_t)l*HH*HH;
        const float* ow = o_w    + (size_t)l*HH*HH;
        const float* gw = gate_w + (size_t)l*HH*II;
        const float* uw = up_w   + (size_t)l*HH*II;
        const float* dw = down_w + (size_t)l*II*HH;

        ln_kernel<<<MM, 256>>>(px, ln1_w + l*HH, ln1_b + l*HH, ph);
        split_act<<<(TACT+255)/256, 256>>>(ph, HH, HH, pa3, 3072, TACT);

        split_w<<<(TWQ+255)/256, 256>>>(qw, HH, HH, HH, pb3, 3072, TWQ);
        bgemm<<<gqkv, 256>>>(pa3, 3072, pb3, 3072, pq, HH, HH, 3072, 0);
        split_w<<<(TWQ+255)/256, 256>>>(kw, HH, HH, HH, pb3, 3072, TWQ);
        bgemm<<<gqkv, 256>>>(pa3, 3072, pb3, 3072, pk, HH, HH, 3072, 0);
        split_w<<<(TWQ+255)/256, 256>>>(vw, HH, HH, HH, pb3, 3072, TWQ);
        bgemm<<<gqkv, 256>>>(pa3, 3072, pb3, 3072, pv, HH, HH, 3072, 0);

        rope2_kernel<<<MM, 512>>>(pq, pk, pq2, pk2);
        attn_kernel<<<gattn, 256>>>(pq2, pk2, pv, ids, pao);

        split_act<<<(TACT+255)/256, 256>>>(pao, HH, HH, pa3, 3072, TACT);
        split_w<<<(TWQ+255)/256, 256>>>(ow, HH, HH, HH, pb3, 3072, TWQ);
        bgemm<<<gqkv, 256>>>(pa3, 3072, pb3, 3072, px, HH, HH, 3072, 1);

        ln_kernel<<<MM, 256>>>(px, ln2_w + l*HH, ln2_b + l*HH, ph);
        split_act<<<(TACT+255)/256, 256>>>(ph, HH, HH, pa3, 3072, TACT);

        split_w<<<(TWGU+255)/256, 256>>>(gw, HH, II, 2816, pb3, 3072, TWGU);
        bgemm<<<ggu, 256>>>(pa3, 3072, pb3, 3072, pg, IPAD, II, 3072, 0);
        split_w<<<(TWGU+255)/256, 256>>>(uw, HH, II, 2816, pb3, 3072, TWGU);
        bgemm<<<ggu, 256>>>(pa3, 3072, pb3, 3072, pu, IPAD, II, 3072, 0);

        silu_kernel<<<gsilu, 256>>>(pg, pu);

        split_act<<<(TACTG+255)/256, 256>>>(pg, IPAD, II, pg3, 8192, TACTG);
        split_w<<<(TWD+255)/256, 256>>>(dw, II, HH, HH, pb3, 8192, TWD);
        bgemm<<<gqkv, 256>>>(pg3, 8192, pb3, 8192, px, HH, HH, 8192, 1);
    }

    ln_kernel<<<MM, 256>>>(px, lnf_w, lnf_b, ph);
    split_act<<<(TACT+255)/256, 256>>>(ph, HH, HH, pa3, 3072, TACT);
    bgemm<<<glog, 256>>>(pa3, 3072, pe3, 3072, out, VV, VV, 3072, 0);
}